// round 3
// baseline (speedup 1.0000x reference)
#include <cuda_runtime.h>
#include <math.h>
#include <stdint.h>

#define BB 4
#define CC 64
#define NP 8192
#define OO 128
#define KNN 20

// ---------------- device scratch ----------------
__device__ float g_xt[(size_t)BB * NP * CC];        // x transposed: [b][n][c]
__device__ float g_xx[BB * NP];                     // squared norms
__device__ float g_uvq[(size_t)BB * NP * 256];      // [b][n][ U(64) | V(64) | Q(128) ]
__device__ int   g_idx[(size_t)BB * NP * KNN];      // top-20 neighbor indices

// ---------------- K0: transpose x (B,C,N) -> xt (B,N,C) ----------------
__global__ void k_transpose(const float* __restrict__ x) {
    __shared__ float tile[32][33];
    int b  = blockIdx.z;
    int c0 = blockIdx.y * 32;
    int n0 = blockIdx.x * 32;
    int tx = threadIdx.x, ty = threadIdx.y;   // 32 x 8
#pragma unroll
    for (int yy = 0; yy < 32; yy += 8)
        tile[ty + yy][tx] = x[((size_t)b * CC + c0 + ty + yy) * NP + n0 + tx];
    __syncthreads();
#pragma unroll
    for (int yy = 0; yy < 32; yy += 8)
        g_xt[((size_t)b * NP + n0 + ty + yy) * CC + c0 + tx] = tile[tx][ty + yy];
}

// ---------------- K0b: squared norms ----------------
__global__ void k_norm() {
    int p = blockIdx.x * blockDim.x + threadIdx.x;
    const float4* v = (const float4*)&g_xt[(size_t)p * CC];
    float s = 0.f;
#pragma unroll
    for (int i = 0; i < 16; i++) {
        float4 q = v[i];
        s += q.x * q.x + q.y * q.y + q.z * q.z + q.w * q.w;
    }
    g_xx[p] = s;
}

// ---------------- K1: precompute U, V, Q per point ----------------
__global__ __launch_bounds__(256) void k_uvq(const float* __restrict__ W1,
                                             const float* __restrict__ W2) {
    __shared__ float xts[16][64];
    int p0 = blockIdx.x * 16;
    int o  = threadIdx.x;
    for (int s = threadIdx.x; s < 16 * 64; s += 256)
        xts[s >> 6][s & 63] = g_xt[(size_t)p0 * 64 + s];

    float4 wr[16];
    if (o < 64) {
        const float* r = W1 + o * 128;
#pragma unroll
        for (int i = 0; i < 16; i++)
            wr[i] = make_float4(r[4*i], r[4*i+1], r[4*i+2], r[4*i+3]);
    } else if (o < 128) {
        const float* r = W1 + (o - 64) * 128;
#pragma unroll
        for (int i = 0; i < 16; i++)
            wr[i] = make_float4(r[64+4*i]-r[4*i], r[65+4*i]-r[4*i+1],
                                r[66+4*i]-r[4*i+2], r[67+4*i]-r[4*i+3]);
    } else {
        const float* r = W2 + (o - 128) * 128;
#pragma unroll
        for (int i = 0; i < 16; i++)
            wr[i] = make_float4(r[64+4*i]-r[4*i], r[65+4*i]-r[4*i+1],
                                r[66+4*i]-r[4*i+2], r[67+4*i]-r[4*i+3]);
    }
    __syncthreads();

    float acc[16];
#pragma unroll
    for (int p = 0; p < 16; p++) acc[p] = 0.f;
#pragma unroll
    for (int c4 = 0; c4 < 16; c4++) {
        float4 w = wr[c4];
#pragma unroll
        for (int p = 0; p < 16; p++) {
            float4 xv = *(const float4*)&xts[p][c4 * 4];
            acc[p] += w.x * xv.x + w.y * xv.y + w.z * xv.z + w.w * xv.w;
        }
    }
#pragma unroll
    for (int p = 0; p < 16; p++)
        g_uvq[((size_t)p0 + p) * 256 + o] = acc[p];
}

// ---------------- K2: kNN top-20 via 128x128 tiled distance GEMM ----------------
// Selection value v(i,j) = 2*dot(xi,xj) - xx_j  (xx_i row-constant: rank-invariant)
#define TI 128
#define TJ 128
#define XI_OFF 0                       // 64 x 132
#define XJ_OFF (64 * 132)              // 64 x 132
#define DS_OFF (2 * 64 * 132)          // 128 x 36
#define XXJ_OFF (DS_OFF + 128 * 36)    // 128
#define SMF (XXJ_OFF + 128)
#define KNN_SMEM_BYTES (SMF * 4)

#define INS(val, jj)                                          \
    do {                                                      \
        float _v = (val);                                     \
        if (_v > minv) {                                      \
            bv[minp] = _v; bi[minp] = (jj);                   \
            minv = bv[0]; minp = 0;                           \
            for (int _t = 1; _t < KNN; _t++)                  \
                if (bv[_t] < minv) { minv = bv[_t]; minp = _t; } \
        }                                                     \
    } while (0)

__global__ void __launch_bounds__(256, 2) k_knn() {
    extern __shared__ float sm[];
    float* xi  = sm + XI_OFF;
    float* xj  = sm + XJ_OFF;
    float* Ds  = sm + DS_OFF;
    float* xxj = sm + XXJ_OFF;

    int b   = blockIdx.y;
    int i0  = blockIdx.x * TI;
    int tid = threadIdx.x;
    int ty  = tid >> 4;    // 0..15
    int tx  = tid & 15;    // 0..15
    size_t base = (size_t)b * NP;

    // i-tile: xi[c][i], stride 132
    for (int s = tid; s < TI * 64; s += 256) {
        int i = s >> 6, c = s & 63;
        xi[c * 132 + i] = g_xt[(base + i0 + i) * 64 + c];
    }

    float bv[KNN]; int bi[KNN];
    float minv = -3.4e38f; int minp = 0;
#pragma unroll
    for (int t = 0; t < KNN; t++) { bv[t] = -3.4e38f; bi[t] = 0; }

    for (int jt = 0; jt < NP; jt += TJ) {
        __syncthreads();   // prior scan of Ds / xj reads done
        for (int s = tid; s < TJ * 64; s += 256) {
            int r = s >> 6, c = s & 63;
            xj[c * 132 + r] = g_xt[(base + jt + r) * 64 + c];
        }
        if (tid < TJ) xxj[tid] = g_xx[base + jt + tid];
        __syncthreads();

        float acc[8][8];
#pragma unroll
        for (int i = 0; i < 8; i++)
#pragma unroll
            for (int j = 0; j < 8; j++) acc[i][j] = 0.f;

#pragma unroll 4
        for (int c = 0; c < 64; c++) {
            float4 a0 = *(const float4*)&xi[c * 132 + 4 * ty];
            float4 a1 = *(const float4*)&xi[c * 132 + 64 + 4 * ty];
            float4 b0 = *(const float4*)&xj[c * 132 + 4 * tx];
            float4 b1 = *(const float4*)&xj[c * 132 + 64 + 4 * tx];
            float av[8] = {a0.x, a0.y, a0.z, a0.w, a1.x, a1.y, a1.z, a1.w};
            float bw[8] = {b0.x, b0.y, b0.z, b0.w, b1.x, b1.y, b1.z, b1.w};
#pragma unroll
            for (int i = 0; i < 8; i++)
#pragma unroll
                for (int j = 0; j < 8; j++)
                    acc[i][j] += av[i] * bw[j];
        }

        // 4 rounds of 32 columns: write D slab, parallel scan by all 256 threads
#pragma unroll
        for (int q = 0; q < 4; q++) {
            if ((tx >> 3) == (q & 1)) {
                int lc = 4 * (tx & 7);          // 0..28 within slab
                int jh = (q >> 1) * 4;          // accumulator col-half base
                float n0 = xxj[32 * q + lc + 0];
                float n1 = xxj[32 * q + lc + 1];
                float n2 = xxj[32 * q + lc + 2];
                float n3 = xxj[32 * q + lc + 3];
#pragma unroll
                for (int ih = 0; ih < 2; ih++)
#pragma unroll
                    for (int i = 0; i < 4; i++) {
                        int row = ih * 64 + 4 * ty + i;
                        float4 dv;
                        dv.x = 2.f * acc[ih * 4 + i][jh + 0] - n0;
                        dv.y = 2.f * acc[ih * 4 + i][jh + 1] - n1;
                        dv.z = 2.f * acc[ih * 4 + i][jh + 2] - n2;
                        dv.w = 2.f * acc[ih * 4 + i][jh + 3] - n3;
                        *(float4*)&Ds[row * 36 + lc] = dv;
                    }
            }
            __syncthreads();
            {
                int row = tid >> 1, sub = tid & 1;
                int jb = jt + 32 * q + 16 * sub;
                const float* p = &Ds[row * 36 + 16 * sub];
#pragma unroll
                for (int m = 0; m < 4; m++) {
                    float4 v = *(const float4*)(p + 4 * m);
                    INS(v.x, jb + 4 * m + 0);
                    INS(v.y, jb + 4 * m + 1);
                    INS(v.z, jb + 4 * m + 2);
                    INS(v.w, jb + 4 * m + 3);
                }
            }
            __syncthreads();
        }
    }

    // merge the two half-lists per row
    __syncthreads();
    float* cv = sm;                      // 128 x 40
    int*   ci = (int*)(sm + 128 * 40);   // 128 x 40
    {
        int row = tid >> 1, sub = tid & 1;
#pragma unroll
        for (int t = 0; t < KNN; t++) {
            cv[row * 40 + sub * 20 + t] = bv[t];
            ci[row * 40 + sub * 20 + t] = bi[t];
        }
    }
    __syncthreads();
    if (tid < 128) {
        float fv[KNN]; int fi[KNN];
        float mv = -3.4e38f; int mp = 0;
#pragma unroll
        for (int t = 0; t < KNN; t++) { fv[t] = -3.4e38f; fi[t] = 0; }
        for (int t = 0; t < 40; t++) {
            float v = cv[tid * 40 + t];
            if (v > mv) {
                fv[mp] = v; fi[mp] = ci[tid * 40 + t];
                mv = fv[0]; mp = 0;
                for (int u = 1; u < KNN; u++)
                    if (fv[u] < mv) { mv = fv[u]; mp = u; }
            }
        }
#pragma unroll
        for (int t = 0; t < KNN; t++)
            g_idx[(base + i0 + tid) * KNN + t] = fi[t];
    }
}

// ---------------- K3: fused gather + softmax gate + output GEMM ----------------
__global__ __launch_bounds__(256) void k_fuse(const float* __restrict__ W2,
                                              float* __restrict__ out) {
    __shared__ float w2as[64 * 128];
    __shared__ float t_s[16][64];
    __shared__ int   idxs[16][KNN];

    int blk = blockIdx.x;
    int b   = blk >> 9;
    int n0  = (blk & 511) * 16;
    int tid = threadIdx.x;
    size_t base = (size_t)b * NP;

    for (int s = tid; s < 8192; s += 256) {
        int o = s >> 6, c = s & 63;
        w2as[c * 128 + o] = W2[o * 128 + c];
    }
    for (int s = tid; s < 16 * KNN; s += 256)
        idxs[s / KNN][s % KNN] = g_idx[(base + n0) * KNN + s];
    __syncthreads();

    for (int pass = 0; pass < 4; pass++) {
        int pt = pass * 4 + (tid >> 6);
        int d  = tid & 63;
        float vv = g_uvq[(base + n0 + pt) * 256 + 64 + d];
        float h[KNN];
#pragma unroll
        for (int k = 0; k < KNN; k++) {
            int j = idxs[pt][k];
            h[k] = g_uvq[(base + j) * 256 + d] + vv;
        }
        float m = h[0];
#pragma unroll
        for (int k = 1; k < KNN; k++) m = fmaxf(m, h[k]);
        float S = 0.f, ws = 0.f;
#pragma unroll
        for (int k = 0; k < KNN; k++) {
            float e = __expf(h[k] - m);
            S += e;
            int j = idxs[pt][k];
            ws += g_xt[(base + j) * 64 + d] * e;
        }
        t_s[pt][d] = ws / S;
    }
    __syncthreads();

    int o = tid & 127, g = tid >> 7;
    float acc[8];
#pragma unroll
    for (int p = 0; p < 8; p++)
        acc[p] = g_uvq[(base + n0 + g * 8 + p) * 256 + 128 + o];
#pragma unroll 8
    for (int c = 0; c < 64; c++) {
        float w = w2as[c * 128 + o];
#pragma unroll
        for (int p = 0; p < 8; p++) acc[p] += w * t_s[g * 8 + p][c];
    }
    float* op = out + ((size_t)b * OO + o) * NP + n0 + g * 8;
    *(float4*)op       = make_float4(acc[0], acc[1], acc[2], acc[3]);
    *(float4*)(op + 4) = make_float4(acc[4], acc[5], acc[6], acc[7]);
}

// ---------------- launch ----------------
extern "C" void kernel_launch(void* const* d_in, const int* in_sizes, int n_in,
                              void* d_out, int out_size) {
    const float* x  = (const float*)d_in[0];
    const float* W1 = (const float*)d_in[1];
    const float* W2 = (const float*)d_in[2];
    float* out = (float*)d_out;

    cudaFuncSetAttribute(k_knn, cudaFuncAttributeMaxDynamicSharedMemorySize,
                         KNN_SMEM_BYTES);

    k_transpose<<<dim3(NP / 32, CC / 32, BB), dim3(32, 8)>>>(x);
    k_norm<<<(BB * NP) / 256, 256>>>();
    k_uvq<<<(BB * NP) / 16, 256>>>(W1, W2);
    k_knn<<<dim3(NP / TI, BB), 256, KNN_SMEM_BYTES>>>();
    k_fuse<<<(BB * NP) / 16, 256>>>(W2, out);
}

// round 4
// speedup vs baseline: 1.3528x; 1.3528x over previous
#include <cuda_runtime.h>
#include <math.h>
#include <stdint.h>

#define BB 4
#define CC 64
#define NP 8192
#define OO 128
#define KNN 20

// ---------------- device scratch ----------------
__device__ float g_xt[(size_t)BB * NP * CC];        // x transposed: [b][n][c]
__device__ float g_xxn[BB * NP];                    // NEGATED half squared norms: -0.5*||x||^2
__device__ float g_uvq[(size_t)BB * NP * 256];      // [b][n][ U(64) | V(64) | Q(128) ]
__device__ int   g_idx[(size_t)BB * NP * KNN];      // top-20 neighbor indices

__device__ __forceinline__ void ffma2(unsigned long long& d,
                                      unsigned long long a,
                                      unsigned long long b) {
    asm("fma.rn.f32x2 %0, %1, %2, %0;" : "+l"(d) : "l"(a), "l"(b));
}
__device__ __forceinline__ void fadd2(unsigned long long& d,
                                      unsigned long long b) {
    asm("add.rn.f32x2 %0, %0, %1;" : "+l"(d) : "l"(b));
}

// ---------------- K0: transpose x (B,C,N) -> xt (B,N,C) ----------------
__global__ void k_transpose(const float* __restrict__ x) {
    __shared__ float tile[32][33];
    int b  = blockIdx.z;
    int c0 = blockIdx.y * 32;
    int n0 = blockIdx.x * 32;
    int tx = threadIdx.x, ty = threadIdx.y;   // 32 x 8
#pragma unroll
    for (int yy = 0; yy < 32; yy += 8)
        tile[ty + yy][tx] = x[((size_t)b * CC + c0 + ty + yy) * NP + n0 + tx];
    __syncthreads();
#pragma unroll
    for (int yy = 0; yy < 32; yy += 8)
        g_xt[((size_t)b * NP + n0 + ty + yy) * CC + c0 + tx] = tile[tx][ty + yy];
}

// ---------------- K0b: negated half squared norms ----------------
__global__ void k_norm() {
    int p = blockIdx.x * blockDim.x + threadIdx.x;
    const float4* v = (const float4*)&g_xt[(size_t)p * CC];
    float s = 0.f;
#pragma unroll
    for (int i = 0; i < 16; i++) {
        float4 q = v[i];
        s += q.x * q.x + q.y * q.y + q.z * q.z + q.w * q.w;
    }
    g_xxn[p] = -0.5f * s;
}

// ---------------- K1: precompute U, V, Q per point ----------------
__global__ __launch_bounds__(256) void k_uvq(const float* __restrict__ W1,
                                             const float* __restrict__ W2) {
    __shared__ float xts[16][64];
    int p0 = blockIdx.x * 16;
    int o  = threadIdx.x;
    for (int s = threadIdx.x; s < 16 * 64; s += 256)
        xts[s >> 6][s & 63] = g_xt[(size_t)p0 * 64 + s];

    float4 wr[16];
    if (o < 64) {
        const float* r = W1 + o * 128;
#pragma unroll
        for (int i = 0; i < 16; i++)
            wr[i] = make_float4(r[4*i], r[4*i+1], r[4*i+2], r[4*i+3]);
    } else if (o < 128) {
        const float* r = W1 + (o - 64) * 128;
#pragma unroll
        for (int i = 0; i < 16; i++)
            wr[i] = make_float4(r[64+4*i]-r[4*i], r[65+4*i]-r[4*i+1],
                                r[66+4*i]-r[4*i+2], r[67+4*i]-r[4*i+3]);
    } else {
        const float* r = W2 + (o - 128) * 128;
#pragma unroll
        for (int i = 0; i < 16; i++)
            wr[i] = make_float4(r[64+4*i]-r[4*i], r[65+4*i]-r[4*i+1],
                                r[66+4*i]-r[4*i+2], r[67+4*i]-r[4*i+3]);
    }
    __syncthreads();

    float acc[16];
#pragma unroll
    for (int p = 0; p < 16; p++) acc[p] = 0.f;
#pragma unroll
    for (int c4 = 0; c4 < 16; c4++) {
        float4 w = wr[c4];
#pragma unroll
        for (int p = 0; p < 16; p++) {
            float4 xv = *(const float4*)&xts[p][c4 * 4];
            acc[p] += w.x * xv.x + w.y * xv.y + w.z * xv.z + w.w * xv.w;
        }
    }
#pragma unroll
    for (int p = 0; p < 16; p++)
        g_uvq[((size_t)p0 + p) * 256 + o] = acc[p];
}

// ---------------- K2: kNN top-20, f32x2 packed distance GEMM ----------------
// Rank value v(i,j) = dot(xi,xj) - 0.5*xx_j   (monotone transform of -dist^2)
#define TI 128
#define TJ 64
#define XI_OFF 0                         // 64 x 260 (i duplicated {v,v})
#define XJ_OFF (64 * 260)                // 64 x 68
#define DS_OFF (XJ_OFF + 64 * 68)        // 128 x 36 (32-col slab)
#define XXN_OFF (DS_OFF + 128 * 36)      // 64
#define SMF (XXN_OFF + 64)
#define KNN_SMEM_BYTES (SMF * 4)

#define INS(val, jj)                                              \
    do {                                                          \
        float _v = (val);                                         \
        if (_v > minv) {                                          \
            bv[minp] = _v; bi[minp] = (jj);                       \
            minv = bv[0]; minp = 0;                               \
            for (int _t = 1; _t < KNN; _t++)                      \
                if (bv[_t] < minv) { minv = bv[_t]; minp = _t; }  \
        }                                                         \
    } while (0)

__global__ void __launch_bounds__(256, 2) k_knn() {
    extern __shared__ float sm[];
    float* xid = sm + XI_OFF;
    float* xj  = sm + XJ_OFF;
    float* Ds  = sm + DS_OFF;
    float* xxn = sm + XXN_OFF;

    int b   = blockIdx.y;
    int i0  = blockIdx.x * TI;
    int tid = threadIdx.x;
    int ty  = tid >> 4;    // 0..15 : i rows 8ty..8ty+7
    int tx  = tid & 15;    // 0..15 : j cols 4tx..4tx+3
    size_t base = (size_t)b * NP;

    // i-tile duplicated: xid[c][2i] = xid[c][2i+1] = xt[i0+i][c]
    for (int s = tid; s < TI * 64; s += 256) {
        int i = s >> 6, c = s & 63;
        float v = g_xt[(base + i0 + i) * 64 + c];
        *(float2*)&xid[c * 260 + 2 * i] = make_float2(v, v);
    }

    // top-k candidate state: lists in LOCAL memory (dynamic index), minv in reg
    float bv[KNN]; int bi[KNN];
    float minv = -3.4e38f; int minp = 0;
    for (int t = 0; t < KNN; t++) { bv[t] = -3.4e38f; bi[t] = 0; }

    const float* pa = xid + 16 * ty;
    const float* pb = xj + 4 * tx;
    int slab = tx >> 3;                 // which 32-col slab this thread writes
    int lc   = 4 * (tx & 7);            // column offset within slab

    __syncthreads();                    // xid ready

    for (int jt = 0; jt < NP; jt += TJ) {
        for (int s = tid; s < TJ * 64; s += 256) {
            int r = s >> 6, c = s & 63;
            xj[c * 68 + r] = g_xt[(base + jt + r) * 64 + c];
        }
        if (tid < TJ) xxn[tid] = g_xxn[base + jt + tid];
        __syncthreads();

        unsigned long long acc[8][2];
#pragma unroll
        for (int i = 0; i < 8; i++) { acc[i][0] = 0ULL; acc[i][1] = 0ULL; }

#pragma unroll 4
        for (int c = 0; c < 64; c++) {
            ulonglong2 A0 = *(const ulonglong2*)(pa + c * 260);
            ulonglong2 A1 = *(const ulonglong2*)(pa + c * 260 + 4);
            ulonglong2 A2 = *(const ulonglong2*)(pa + c * 260 + 8);
            ulonglong2 A3 = *(const ulonglong2*)(pa + c * 260 + 12);
            ulonglong2 Bv = *(const ulonglong2*)(pb + c * 68);
            ffma2(acc[0][0], A0.x, Bv.x); ffma2(acc[0][1], A0.x, Bv.y);
            ffma2(acc[1][0], A0.y, Bv.x); ffma2(acc[1][1], A0.y, Bv.y);
            ffma2(acc[2][0], A1.x, Bv.x); ffma2(acc[2][1], A1.x, Bv.y);
            ffma2(acc[3][0], A1.y, Bv.x); ffma2(acc[3][1], A1.y, Bv.y);
            ffma2(acc[4][0], A2.x, Bv.x); ffma2(acc[4][1], A2.x, Bv.y);
            ffma2(acc[5][0], A2.y, Bv.x); ffma2(acc[5][1], A2.y, Bv.y);
            ffma2(acc[6][0], A3.x, Bv.x); ffma2(acc[6][1], A3.x, Bv.y);
            ffma2(acc[7][0], A3.y, Bv.x); ffma2(acc[7][1], A3.y, Bv.y);
        }

        // two 32-col slabs: write (with packed norm add), then all-thread scan
#pragma unroll
        for (int q = 0; q < 2; q++) {
            if (slab == q) {
                ulonglong2 hx = *(const ulonglong2*)&xxn[32 * q + lc];
#pragma unroll
                for (int i = 0; i < 8; i++) {
                    union { unsigned long long u[2]; float4 f; } U;
                    unsigned long long s0 = acc[i][0], s1 = acc[i][1];
                    fadd2(s0, hx.x); fadd2(s1, hx.y);
                    U.u[0] = s0; U.u[1] = s1;
                    *(float4*)&Ds[(8 * ty + i) * 36 + lc] = U.f;
                }
            }
            __syncthreads();
            {
                int row = tid >> 1, sub = tid & 1;
                int jb = jt + 32 * q + 16 * sub;
                const float* p = &Ds[row * 36 + 16 * sub];
#pragma unroll
                for (int m = 0; m < 4; m++) {
                    float4 v = *(const float4*)(p + 4 * m);
                    INS(v.x, jb + 4 * m + 0);
                    INS(v.y, jb + 4 * m + 1);
                    INS(v.z, jb + 4 * m + 2);
                    INS(v.w, jb + 4 * m + 3);
                }
            }
            __syncthreads();
        }
    }

    // merge the two half-lists per row
    float* cv = sm;                      // 128 x 40
    int*   ci = (int*)(sm + 128 * 40);   // 128 x 40
    {
        int row = tid >> 1, sub = tid & 1;
        for (int t = 0; t < KNN; t++) {
            cv[row * 40 + sub * 20 + t] = bv[t];
            ci[row * 40 + sub * 20 + t] = bi[t];
        }
    }
    __syncthreads();
    if (tid < 128) {
        float fv[KNN]; int fi[KNN];
        float mv = -3.4e38f; int mp = 0;
        for (int t = 0; t < KNN; t++) { fv[t] = -3.4e38f; fi[t] = 0; }
        for (int t = 0; t < 40; t++) {
            float v = cv[tid * 40 + t];
            if (v > mv) {
                fv[mp] = v; fi[mp] = ci[tid * 40 + t];
                mv = fv[0]; mp = 0;
                for (int u = 1; u < KNN; u++)
                    if (fv[u] < mv) { mv = fv[u]; mp = u; }
            }
        }
        for (int t = 0; t < KNN; t++)
            g_idx[(base + i0 + tid) * KNN + t] = fi[t];
    }
}

// ---------------- K3: fused gather + softmax gate + output GEMM ----------------
__global__ __launch_bounds__(256) void k_fuse(const float* __restrict__ W2,
                                              float* __restrict__ out) {
    __shared__ float w2as[64 * 128];
    __shared__ float t_s[16][64];
    __shared__ int   idxs[16][KNN];

    int blk = blockIdx.x;
    int b   = blk >> 9;
    int n0  = (blk & 511) * 16;
    int tid = threadIdx.x;
    size_t base = (size_t)b * NP;

    for (int s = tid; s < 8192; s += 256) {
        int o = s >> 6, c = s & 63;
        w2as[c * 128 + o] = W2[o * 128 + c];
    }
    for (int s = tid; s < 16 * KNN; s += 256)
        idxs[s / KNN][s % KNN] = g_idx[(base + n0) * KNN + s];
    __syncthreads();

    for (int pass = 0; pass < 4; pass++) {
        int pt = pass * 4 + (tid >> 6);
        int d  = tid & 63;
        float vv = g_uvq[(base + n0 + pt) * 256 + 64 + d];
        float h[KNN];
#pragma unroll
        for (int k = 0; k < KNN; k++) {
            int j = idxs[pt][k];
            h[k] = g_uvq[(base + j) * 256 + d] + vv;
        }
        float m = h[0];
#pragma unroll
        for (int k = 1; k < KNN; k++) m = fmaxf(m, h[k]);
        float S = 0.f, ws = 0.f;
#pragma unroll
        for (int k = 0; k < KNN; k++) {
            float e = __expf(h[k] - m);
            S += e;
            int j = idxs[pt][k];
            ws += g_xt[(base + j) * 64 + d] * e;
        }
        t_s[pt][d] = ws / S;
    }
    __syncthreads();

    int o = tid & 127, g = tid >> 7;
    float acc[8];
#pragma unroll
    for (int p = 0; p < 8; p++)
        acc[p] = g_uvq[(base + n0 + g * 8 + p) * 256 + 128 + o];
#pragma unroll 8
    for (int c = 0; c < 64; c++) {
        float w = w2as[c * 128 + o];
#pragma unroll
        for (int p = 0; p < 8; p++) acc[p] += w * t_s[g * 8 + p][c];
    }
    float* op = out + ((size_t)b * OO + o) * NP + n0 + g * 8;
    *(float4*)op       = make_float4(acc[0], acc[1], acc[2], acc[3]);
    *(float4*)(op + 4) = make_float4(acc[4], acc[5], acc[6], acc[7]);
}

// ---------------- launch ----------------
extern "C" void kernel_launch(void* const* d_in, const int* in_sizes, int n_in,
                              void* d_out, int out_size) {
    const float* x  = (const float*)d_in[0];
    const float* W1 = (const float*)d_in[1];
    const float* W2 = (const float*)d_in[2];
    float* out = (float*)d_out;

    cudaFuncSetAttribute(k_knn, cudaFuncAttributeMaxDynamicSharedMemorySize,
                         KNN_SMEM_BYTES);

    k_transpose<<<dim3(NP / 32, CC / 32, BB), dim3(32, 8)>>>(x);
    k_norm<<<(BB * NP) / 256, 256>>>();
    k_uvq<<<(BB * NP) / 16, 256>>>(W1, W2);
    k_knn<<<dim3(NP / TI, BB), 256, KNN_SMEM_BYTES>>>();
    k_fuse<<<(BB * NP) / 16, 256>>>(W2, out);
}